// round 12
// baseline (speedup 1.0000x reference)
#include <cuda_runtime.h>
#include <cuda_bf16.h>
#include <cstdint>

// q,k,v: [2,12,2048,64] f32; mask: [2,1,1,2048] i32; bias: [1,12,2048,2048] f32
// out region: out [2,12,2048,64] then attn [2,12,2048,2048]
// attn = softmax((q/8)@k^T + bias, masked -> -10000); out = attn @ v
// Base = R11 (428us). R12 delta: QK emulation 3-term bf16 -> SINGLE-TERM fp16
// (q/T, k both well inside fp16 range; fp32 MMA accum; logit err ~4e-4 abs).
// Halves MMA count, halves QK LDSM, removes Qlo/Klo buffers + their converts.
// PV stays fp16 with 2^-5 pre-scale. Normalize fused. mma.sync path (no tcgen05).

#define TEMPERATURE 8.0f
#define NEG_FILL -10000.0f
#define ESCALE 0.03125f
#define ESCALE_INV 32.0f

constexpr int B_ = 2, H_ = 12, S_ = 2048, D_ = 64;
constexpr int TQ = 128, TK = 64;
constexpr int NKT = S_ / TK;      // 32
constexpr int LDT = 72;           // fp16 row stride (padded)
constexpr int F16_BYTES = (TQ * LDT + 2 * TK * LDT) * 2;   // Qh + Kh + Vh = 36864
constexpr int RAW_BYTES = 2 * TK * D_ * 4;                  // 32768
constexpr int SMEM_BYTES = F16_BYTES + RAW_BYTES;           // 69632 -> 2 blocks/SM

// ---------- PTX helpers ----------
__device__ __forceinline__ uint32_t smem_u32(const void* p) {
    return (uint32_t)__cvta_generic_to_shared(p);
}
__device__ __forceinline__ uint32_t pack_f16(float a, float b) {    // a -> low half
    uint32_t r;
    asm("cvt.rn.f16x2.f32 %0, %1, %2;" : "=r"(r) : "f"(b), "f"(a));
    return r;
}
__device__ __forceinline__ void ldsm_x4(uint32_t addr, uint32_t& r0, uint32_t& r1,
                                        uint32_t& r2, uint32_t& r3) {
    asm volatile("ldmatrix.sync.aligned.m8n8.x4.shared.b16 {%0,%1,%2,%3}, [%4];"
                 : "=r"(r0), "=r"(r1), "=r"(r2), "=r"(r3) : "r"(addr));
}
__device__ __forceinline__ void ldsm_x4t(uint32_t addr, uint32_t& r0, uint32_t& r1,
                                         uint32_t& r2, uint32_t& r3) {
    asm volatile("ldmatrix.sync.aligned.m8n8.x4.trans.shared.b16 {%0,%1,%2,%3}, [%4];"
                 : "=r"(r0), "=r"(r1), "=r"(r2), "=r"(r3) : "r"(addr));
}
// NOT volatile -> ptxas may reschedule to hide HMMA latency.
__device__ __forceinline__ void mma_f16(float* c,
                                        uint32_t a0, uint32_t a1, uint32_t a2, uint32_t a3,
                                        uint32_t b0, uint32_t b1) {
    asm("mma.sync.aligned.m16n8k16.row.col.f32.f16.f16.f32 "
        "{%0,%1,%2,%3}, {%4,%5,%6,%7}, {%8,%9}, {%0,%1,%2,%3};"
        : "+f"(c[0]), "+f"(c[1]), "+f"(c[2]), "+f"(c[3])
        : "r"(a0), "r"(a1), "r"(a2), "r"(a3), "r"(b0), "r"(b1));
}
__device__ __forceinline__ void cp_async16(uint32_t saddr, const void* gaddr) {
    asm volatile("cp.async.cg.shared.global [%0], [%1], 16;" :: "r"(saddr), "l"(gaddr));
}
__device__ __forceinline__ void cp_commit() {
    asm volatile("cp.async.commit_group;" ::: "memory");
}
__device__ __forceinline__ void cp_wait_all() {
    asm volatile("cp.async.wait_group 0;" ::: "memory");
}

// ============== Fused kernel: e=exp(logits), rowsums, out, attn normalize =======
__global__ __launch_bounds__(256, 2) void attn_k1(
    const float* __restrict__ q, const float* __restrict__ k,
    const float* __restrict__ v, const int* __restrict__ mask,
    const float* __restrict__ bias, float* __restrict__ out,
    float* __restrict__ attn)
{
    extern __shared__ char smraw[];
    __shared__ float row_inv[TQ];
    __half* sm = (__half*)smraw;

    __half* Qh = sm;                      // [128][72] fp16
    __half* Kh = Qh + TQ * LDT;           // [64][72]
    __half* Vh = Kh + TK * LDT;           // [64][72]
    float* rawK = (float*)(smraw + F16_BYTES);
    float* rawV = rawK + TK * D_;

    const int t    = threadIdx.x;
    const int lane = t & 31;
    const int w    = t >> 5;
    const int bh   = blockIdx.y;
    const int b    = bh & 1;              // b innermost -> bias shared in L2
    const int h    = bh >> 1;
    const int q0   = blockIdx.x * TQ;
    const int bhq  = b * H_ + h;

    const float* qb    = q    + ((long)bhq * S_ + q0) * D_;
    const float* kb    = k    + (long)bhq * S_ * D_;
    const float* vb    = v    + (long)bhq * S_ * D_;
    const int*   maskb = mask + (long)b * S_;
    float*       attb  = attn + ((long)bhq * S_ + q0) * S_;
    const float* biasb = bias + ((long)h  * S_ + q0) * S_;

    // ---- prologue: stage tile 0 K/V raw via cp.async ----
    const uint32_t rawK_a = smem_u32(rawK);
    const uint32_t rawV_a = smem_u32(rawV);
    #pragma unroll
    for (int i = 0; i < 4; i++) {
        int idx4 = t + i * 256;
        cp_async16(rawK_a + idx4 * 16u, kb + idx4 * 4);
        cp_async16(rawV_a + idx4 * 16u, vb + idx4 * 4);
    }
    cp_commit();

    // ---- load Q (scaled) as fp16 ----
    #pragma unroll
    for (int i = 0; i < 8; i++) {
        int idx4 = t + i * 256;
        int r  = idx4 >> 4;
        int d4 = (idx4 & 15) * 4;
        float4 qv = *(const float4*)(qb + (long)r * D_ + d4);
        uint32_t* ph = (uint32_t*)(Qh + r * LDT + d4);
        ph[0] = pack_f16(qv.x * (1.0f / TEMPERATURE), qv.y * (1.0f / TEMPERATURE));
        ph[1] = pack_f16(qv.z * (1.0f / TEMPERATURE), qv.w * (1.0f / TEMPERATURE));
    }

    const int mrow = w * 16;
    const int g    = lane >> 2;
    const int qr0  = mrow + g;
    const int qr1  = qr0 + 8;

    const uint32_t qa_off = ((uint32_t)(mrow + (lane & 15)) * LDT + 8u * (lane >> 4)) * 2u;
    const uint32_t qh_base = smem_u32(Qh) + qa_off;
    const int kgrp = lane >> 3;
    const uint32_t kx4_off =
        ((uint32_t)((kgrp >> 1) * 8 + (lane & 7)) * LDT + (uint32_t)(kgrp & 1) * 8u) * 2u;
    const uint32_t kh_b = smem_u32(Kh) + kx4_off;
    const uint32_t vx4_off =
        ((uint32_t)(lane & 15) * LDT + (uint32_t)(lane >> 4) * 8u) * 2u;
    const uint32_t vh_b = smem_u32(Vh) + vx4_off;

    float accO[8][4];
    #pragma unroll
    for (int i = 0; i < 8; i++)
        #pragma unroll
        for (int j = 0; j < 4; j++) accO[i][j] = 0.0f;
    float sum0 = 0.0f, sum1 = 0.0f;

    for (int kt = 0; kt < NKT; kt++) {
        const int k0 = kt * TK;
        cp_wait_all();
        __syncthreads();

        // ---- convert raw (smem) -> K fp16, V fp16 ----
        #pragma unroll
        for (int i = 0; i < 4; i++) {
            int idx4 = t + i * 256;
            int r  = idx4 >> 4;
            int d4 = (idx4 & 15) * 4;
            float4 kv = *(const float4*)(rawK + idx4 * 4);
            uint32_t* ph = (uint32_t*)(Kh + r * LDT + d4);
            ph[0] = pack_f16(kv.x, kv.y); ph[1] = pack_f16(kv.z, kv.w);
            float4 vv = *(const float4*)(rawV + idx4 * 4);
            uint32_t* pv = (uint32_t*)(Vh + r * LDT + d4);
            pv[0] = pack_f16(vv.x, vv.y); pv[1] = pack_f16(vv.z, vv.w);
        }
        __syncthreads();

        // ---- stage next tile's raw K/V (overlaps MMAs) ----
        if (kt + 1 < NKT) {
            const float* knext = kb + (long)(k0 + TK) * D_;
            const float* vnext = vb + (long)(k0 + TK) * D_;
            #pragma unroll
            for (int i = 0; i < 4; i++) {
                int idx4 = t + i * 256;
                cp_async16(rawK_a + idx4 * 16u, knext + idx4 * 4);
                cp_async16(rawV_a + idx4 * 16u, vnext + idx4 * 4);
            }
            cp_commit();
        }

        // ---- QK^T: single-term fp16, 32 MMAs/warp ----
        float acc[8][4];
        #pragma unroll
        for (int i = 0; i < 8; i++)
            #pragma unroll
            for (int j = 0; j < 4; j++) acc[i][j] = 0.0f;

        #pragma unroll
        for (int ks = 0; ks < 4; ks++) {
            uint32_t a0, a1, a2, a3;
            ldsm_x4(qh_base + ks * 32u, a0, a1, a2, a3);
            #pragma unroll
            for (int hg = 0; hg < 2; hg++) {            // 4 n-tiles per group
                const int nt0 = hg * 4;
                const uint32_t o0 = (uint32_t)(nt0 * 8 * LDT) * 2u + ks * 32u;
                const uint32_t o1 = (uint32_t)((nt0 + 2) * 8 * LDT) * 2u + ks * 32u;
                uint32_t kh[8];
                ldsm_x4(kh_b + o0, kh[0], kh[1], kh[2], kh[3]);
                ldsm_x4(kh_b + o1, kh[4], kh[5], kh[6], kh[7]);
                mma_f16(acc[nt0 + 0], a0, a1, a2, a3, kh[0], kh[1]);
                mma_f16(acc[nt0 + 1], a0, a1, a2, a3, kh[2], kh[3]);
                mma_f16(acc[nt0 + 2], a0, a1, a2, a3, kh[4], kh[5]);
                mma_f16(acc[nt0 + 3], a0, a1, a2, a3, kh[6], kh[7]);
            }
        }

        // ---- epilogue: bias, mask, exp, write e, build fp16 PV A-frags ----
        uint32_t efr[8][2];
        #pragma unroll
        for (int nt = 0; nt < 8; nt++) {
            const int gk = k0 + nt * 8 + (lane & 3) * 2;
            const int2 mv = *(const int2*)(maskb + gk);
            float2 bv0 = *(const float2*)(biasb + (long)qr0 * S_ + gk);
            float2 bv1 = *(const float2*)(biasb + (long)qr1 * S_ + gk);
            float l00 = acc[nt][0] + bv0.x; if (mv.x == 0) l00 = NEG_FILL;
            float l01 = acc[nt][1] + bv0.y; if (mv.y == 0) l01 = NEG_FILL;
            float l10 = acc[nt][2] + bv1.x; if (mv.x == 0) l10 = NEG_FILL;
            float l11 = acc[nt][3] + bv1.y; if (mv.y == 0) l11 = NEG_FILL;
            float e00 = __expf(l00), e01 = __expf(l01);
            float e10 = __expf(l10), e11 = __expf(l11);
            sum0 += e00 + e01;
            sum1 += e10 + e11;
            *(float2*)(attb + (long)qr0 * S_ + gk) = make_float2(e00, e01);
            *(float2*)(attb + (long)qr1 * S_ + gk) = make_float2(e10, e11);
            efr[nt][0] = pack_f16(e00 * ESCALE, e01 * ESCALE);
            efr[nt][1] = pack_f16(e10 * ESCALE, e11 * ESCALE);
        }

        // ---- PV: out[16 x 64] += E[16 x 64] @ V[64 x 64], fp16 ----
        #pragma unroll
        for (int ks2 = 0; ks2 < 4; ks2++) {
            uint32_t a0 = efr[2 * ks2][0],     a1 = efr[2 * ks2][1];
            uint32_t a2 = efr[2 * ks2 + 1][0], a3 = efr[2 * ks2 + 1][1];
            const uint32_t roff = (uint32_t)(ks2 * 16 * LDT) * 2u;
            #pragma unroll
            for (int dnp = 0; dnp < 8; dnp += 2) {
                uint32_t b0, b1, b2, b3;
                ldsm_x4t(vh_b + roff + dnp * 16u, b0, b1, b2, b3);
                mma_f16(accO[dnp],     a0, a1, a2, a3, b0, b1);
                mma_f16(accO[dnp + 1], a0, a1, a2, a3, b2, b3);
            }
        }
    }

    // ---- row sums: quad-reduce ----
    sum0 += __shfl_xor_sync(0xffffffffu, sum0, 1);
    sum0 += __shfl_xor_sync(0xffffffffu, sum0, 2);
    sum1 += __shfl_xor_sync(0xffffffffu, sum1, 1);
    sum1 += __shfl_xor_sync(0xffffffffu, sum1, 2);
    const float inv0 = 1.0f / sum0;
    const float inv1 = 1.0f / sum1;
    if ((lane & 3) == 0) {
        row_inv[qr0] = inv0;
        row_inv[qr1] = inv1;
    }

    // ---- write out (normalized; ESCALE_INV undoes fp16 pre-scale) ----
    #pragma unroll
    for (int dn = 0; dn < 8; dn++) {
        const int dc = dn * 8 + (lane & 3) * 2;
        *(float2*)(out + ((long)bhq * S_ + q0 + qr0) * D_ + dc) =
            make_float2(accO[dn][0] * inv0 * ESCALE_INV, accO[dn][1] * inv0 * ESCALE_INV);
        *(float2*)(out + ((long)bhq * S_ + q0 + qr1) * D_ + dc) =
            make_float2(accO[dn][2] * inv1 * ESCALE_INV, accO[dn][3] * inv1 * ESCALE_INV);
    }

    // ---- fused normalize: scale own 128 attn rows in place ----
    __syncthreads();
    float4* ab4 = (float4*)attb;
    #pragma unroll 4
    for (int i4 = t; i4 < TQ * S_ / 4; i4 += 256) {
        const float inv = row_inv[i4 >> 9];
        float4 x = ab4[i4];
        x.x *= inv; x.y *= inv; x.z *= inv; x.w *= inv;
        ab4[i4] = x;
    }
}

extern "C" void kernel_launch(void* const* d_in, const int* in_sizes, int n_in,
                              void* d_out, int out_size) {
    const float* q    = (const float*)d_in[0];
    const float* k    = (const float*)d_in[1];
    const float* v    = (const float*)d_in[2];
    const int*   mask = (const int*)  d_in[3];
    const float* bias = (const float*)d_in[4];

    float* out  = (float*)d_out;
    float* attn = (float*)d_out + (long)B_ * H_ * S_ * D_;

    static int configured = 0;
    if (!configured) {
        cudaFuncSetAttribute(attn_k1,
                             cudaFuncAttributeMaxDynamicSharedMemorySize, SMEM_BYTES);
        configured = 1;
    }

    dim3 grid(S_ / TQ, B_ * H_);        // (16, 24)
    attn_k1<<<grid, 256, SMEM_BYTES>>>(q, k, v, mask, bias, out, attn);
}